// round 7
// baseline (speedup 1.0000x reference)
#include <cuda_runtime.h>
#include <cuda_fp16.h>
#include <math.h>

#define NN 50000
#define EE 1600000
#define DD 128
#define HC 64     // H*C = 2*32
#define NB 196    // ceil(NN/256) scan blocks

// ---- scratch (device globals; no allocation allowed) ----
__device__ __half  g_hh[NN * HC];       // fp16 h = elu(x) @ W      6.4 MB
__device__ float   g_asrc[NN * 2];
__device__ float   g_adst[NN * 2];
__device__ float2  g_nwcnt[NN];         // {sum w, count} per source node
__device__ int     g_deg[NN];           // in-degree (excl self loop)
__device__ int     g_cursor[NN];        // scan result, then scatter cursors (end after scatter)
__device__ int     g_flag[NB];          // lookback flags (reset by k_hist)
__device__ uint2   g_sorted[EE];        // {src, as01:half2}  12.8 MB

__device__ __forceinline__ float lrelu(float a) { return a > 0.0f ? a : 0.2f * a; }
__device__ __forceinline__ float elu_f(float v) { return v > 0.0f ? v : (__expf(v) - 1.0f); }

__device__ __forceinline__ void fma4(float4& acc, const float4 wv, const float xs) {
    acc.x += xs * wv.x; acc.y += xs * wv.y; acc.z += xs * wv.z; acc.w += xs * wv.w;
}
__device__ __forceinline__ float dot4(const float4 a, const float4 b) {
    return a.x*b.x + a.y*b.y + a.z*b.z + a.w*b.w;
}

// ---------------- 1) h = elu(x) @ W, register-blocked 4x8, fused attention dots ----------------
__global__ void k_gemm(const float* __restrict__ x, const float* __restrict__ W,
                       const float* __restrict__ att_src, const float* __restrict__ att_dst) {
    __shared__ float sW[DD * HC];                 // 32 KB
    __shared__ float sAs[HC], sAd[HC];
    int tid = threadIdx.x;                        // 256 threads
    const float4* Wv = (const float4*)W;
    float4* sWv = (float4*)sW;
#pragma unroll
    for (int i = 0; i < 8; i++) sWv[tid + i * 256] = Wv[tid + i * 256];
    if (tid < HC) { sAs[tid] = att_src[tid]; sAd[tid] = att_dst[tid]; }
    __syncthreads();

    int cg = tid & 7;                             // 8 cols starting at cg*8
    int rg = tid >> 3;                            // 0..31, 4 rows each
    int rb = blockIdx.x * 128 + rg * 4;

    float4 a[4][2];
#pragma unroll
    for (int i = 0; i < 4; i++) { a[i][0] = make_float4(0,0,0,0); a[i][1] = make_float4(0,0,0,0); }

    const float4* xp[4];
#pragma unroll
    for (int i = 0; i < 4; i++) {
        int r = rb + i; if (r >= NN) r = NN - 1;
        xp[i] = (const float4*)(x + (size_t)r * DD);
    }

#pragma unroll 2
    for (int k4 = 0; k4 < 32; k4++) {
        float4 xv[4];
#pragma unroll
        for (int i = 0; i < 4; i++) {
            float4 v = __ldg(&xp[i][k4]);
            v.x = elu_f(v.x); v.y = elu_f(v.y); v.z = elu_f(v.z); v.w = elu_f(v.w);
            xv[i] = v;
        }
#pragma unroll
        for (int j = 0; j < 4; j++) {
            const float4* wr = (const float4*)&sW[(k4 * 4 + j) * HC + cg * 8];
            float4 w0 = wr[0], w1 = wr[1];
#pragma unroll
            for (int i = 0; i < 4; i++) {
                float xs = (j == 0) ? xv[i].x : (j == 1) ? xv[i].y : (j == 2) ? xv[i].z : xv[i].w;
                fma4(a[i][0], w0, xs);
                fma4(a[i][1], w1, xs);
            }
        }
    }

    float4 s0 = ((const float4*)sAs)[cg * 2], s1 = ((const float4*)sAs)[cg * 2 + 1];
    float4 d0 = ((const float4*)sAd)[cg * 2], d1 = ((const float4*)sAd)[cg * 2 + 1];
    float asp[4], adp[4];
#pragma unroll
    for (int i = 0; i < 4; i++) {
        asp[i] = dot4(a[i][0], s0) + dot4(a[i][1], s1);
        adp[i] = dot4(a[i][0], d0) + dot4(a[i][1], d1);
    }
#pragma unroll
    for (int off = 1; off <= 2; off <<= 1) {
#pragma unroll
        for (int i = 0; i < 4; i++) {
            asp[i] += __shfl_xor_sync(0xffffffff, asp[i], off);
            adp[i] += __shfl_xor_sync(0xffffffff, adp[i], off);
        }
    }
    if ((cg & 3) == 0) {
        int head = cg >> 2;
#pragma unroll
        for (int i = 0; i < 4; i++) {
            int r = rb + i;
            if (r < NN) {
                g_asrc[2*r + head] = asp[i];
                g_adst[2*r + head] = adp[i];
                if (head == 0) { g_nwcnt[r] = make_float2(0.0f, 0.0f); g_deg[r] = 0; }
            }
        }
    }

#pragma unroll
    for (int i = 0; i < 4; i++) {
        int r = rb + i;
        if (r < NN) {
            __half2* hp = (__half2*)(g_hh + (size_t)r * HC + cg * 8);
            hp[0] = __floats2half2_rn(a[i][0].x, a[i][0].y);
            hp[1] = __floats2half2_rn(a[i][0].z, a[i][0].w);
            hp[2] = __floats2half2_rn(a[i][1].x, a[i][1].y);
            hp[3] = __floats2half2_rn(a[i][1].z, a[i][1].w);
        }
    }
}

// ---------------- 2) histogram: deg[dst]++, nwcnt[src] += {w,1}; reset scan flags ----------------
__global__ void k_hist(const int* __restrict__ ei, const float* __restrict__ wgt) {
    int e = blockIdx.x * blockDim.x + threadIdx.x;
    if (threadIdx.x == 0 && blockIdx.x < NB) g_flag[blockIdx.x] = INT_MIN;
    if (e >= EE) return;
    int s = __ldg(&ei[e]);
    int d = __ldg(&ei[EE + e]);
    atomicAdd(&g_deg[d], 1);
    float w = __ldg(&wgt[e]);
    asm volatile("red.global.add.v2.f32 [%0], {%1,%2};"
                 :: "l"((float*)(g_nwcnt + s)), "f"(w), "f"(1.0f) : "memory");
}

// ---------------- 3) single-pass exclusive scan with chained lookback ----------------
__global__ void k_scan() {
    int tid = threadIdx.x, lane = tid & 31, w = tid >> 5;
    int i = blockIdx.x * 256 + tid;
    int v = (i < NN) ? g_deg[i] : 0;
    int s = v;
#pragma unroll
    for (int off = 1; off < 32; off <<= 1) {
        int t = __shfl_up_sync(0xffffffff, s, off);
        if (lane >= off) s += t;
    }
    __shared__ int ws[8];
    __shared__ int s_prev;
    if (lane == 31) ws[w] = s;
    __syncthreads();
    int woff = 0;
#pragma unroll
    for (int k = 0; k < 8; k++) woff += (k < w) ? ws[k] : 0;
    if (tid == 0) {
        int tot = 0;
#pragma unroll
        for (int k = 0; k < 8; k++) tot += ws[k];
        int prev = 0;
        if (blockIdx.x > 0) {
            do { prev = atomicAdd(&g_flag[blockIdx.x - 1], 0); } while (prev == INT_MIN);
        }
        atomicExch(&g_flag[blockIdx.x], prev + tot);
        s_prev = prev;
    }
    __syncthreads();
    if (i < NN) g_cursor[i] = s - v + woff + s_prev;
}

// ---------------- 4) scatter: 8B records {src, as01:half2} sorted by dst ----------------
__global__ void k_scatter(const int* __restrict__ ei) {
    int e = blockIdx.x * blockDim.x + threadIdx.x;
    if (e >= EE) return;
    int s = __ldg(&ei[e]);
    int d = __ldg(&ei[EE + e]);
    float2 as = __ldg((const float2*)(g_asrc + 2 * s));
    __half2 ah = __floats2half2_rn(as.x, as.y);
    uint2 rec;
    rec.x = (unsigned)s;
    rec.y = *(unsigned*)&ah;
    int pos = atomicAdd(&g_cursor[d], 1);
    g_sorted[pos] = rec;
}

// ---------------- 5) gather: one warp per dst, exp via lane-slot trick, pipelined ----------------
__global__ void k_gather(float* __restrict__ out, const float* __restrict__ bias,
                         const float* __restrict__ esc) {
    int warp_in_block = threadIdx.x >> 5;
    int lane = threadIdx.x & 31;
    int n = blockIdx.x * 8 + warp_in_block;
    if (n >= NN) return;

    int head = lane >> 4;                 // lanes 0-15: head0, 16-31: head1
    int cnt   = g_deg[n];
    int start = g_cursor[n] - cnt;        // cursor is end-of-segment after scatter

    float2 adv = __ldg((const float2*)(g_adst + 2 * n));
    int t  = lane & 7;
    int qq = t >> 1;                      // record slot this lane computes exp for
    int hs = t & 1;                       // head slot
    float ad_sel = hs ? adv.y : adv.x;
    float ad_me  = head ? adv.y : adv.x;

    float2 acc = make_float2(0.0f, 0.0f);
    float den = 0.0f;
    const __half2* hh = (const __half2*)g_hh;
    const uint2* rec = g_sorted + start;

    int nq = cnt >> 2, rem = cnt & 3;
    uint2 r0, r1, r2, r3;
    if (nq) { r0 = __ldg(rec); r1 = __ldg(rec + 1); r2 = __ldg(rec + 2); r3 = __ldg(rec + 3); }
    for (int q = 0; q < nq; q++) {
        __half2 v0 = __ldg(hh + (size_t)r0.x * 32 + lane);
        __half2 v1 = __ldg(hh + (size_t)r1.x * 32 + lane);
        __half2 v2 = __ldg(hh + (size_t)r2.x * 32 + lane);
        __half2 v3 = __ldg(hh + (size_t)r3.x * 32 + lane);

        // one warp-wide exp computes all 8 (record, head) slots in lanes 0-7
        unsigned ab = (qq == 0) ? r0.y : (qq == 1) ? r1.y : (qq == 2) ? r2.y : r3.y;
        float2 af = __half22float2(*(__half2*)&ab);
        float ev = __expf(lrelu((hs ? af.y : af.x) + ad_sel));
        float e0 = __shfl_sync(0xffffffff, ev, head);
        float e1 = __shfl_sync(0xffffffff, ev, 2 + head);
        float e2 = __shfl_sync(0xffffffff, ev, 4 + head);
        float e3 = __shfl_sync(0xffffffff, ev, 6 + head);

        bool more = (q + 1 < nq);
        uint2 n0, n1, n2, n3;
        if (more) {
            const uint2* p = rec + 4 * (q + 1);
            n0 = __ldg(p); n1 = __ldg(p + 1); n2 = __ldg(p + 2); n3 = __ldg(p + 3);
        }
        float2 f0 = __half22float2(v0);
        float2 f1 = __half22float2(v1);
        float2 f2 = __half22float2(v2);
        float2 f3 = __half22float2(v3);
        acc.x += e0 * f0.x + e1 * f1.x + e2 * f2.x + e3 * f3.x;
        acc.y += e0 * f0.y + e1 * f1.y + e2 * f2.y + e3 * f3.y;
        den   += (e0 + e1) + (e2 + e3);
        if (more) { r0 = n0; r1 = n1; r2 = n2; r3 = n3; }
    }
    const uint2* tp = rec + nq * 4;
    for (int k = 0; k < rem; k++) {
        uint2 r = __ldg(tp + k);
        __half2 v = __ldg(hh + (size_t)r.x * 32 + lane);
        float2 af = __half22float2(*(__half2*)&r.y);
        float e0 = __expf(lrelu((head ? af.y : af.x) + ad_me));
        float2 f = __half22float2(v);
        acc.x += e0 * f.x; acc.y += e0 * f.y;
        den += e0;
    }

    // self loop (fp32 logits)
    float a_self = lrelu(g_asrc[2*n + head] + ad_me);
    float e_self = __expf(a_self);
    float2 hsv = __half22float2(__ldg(hh + (size_t)n * 32 + lane));
    acc.x += e_self * hsv.x; acc.y += e_self * hsv.y;
    den += e_self;

    float rd = __frcp_rn(den);

    float2 nwc = g_nwcnt[n];
    float nw = nwc.x / fmaxf(nwc.y, 1.0f);
    nw = fminf(fmaxf(nw, 0.2f), 5.0f);
    float sf  = 0.1f / (1.0f + __expf(-esc[0]));
    float add = sf * (nw - 1.0f);

    float2 b2 = *(const float2*)(bias + 2 * lane);
    float2 o;
    o.x = acc.x * rd + b2.x + add;
    o.y = acc.y * rd + b2.y + add;
    *(float2*)(out + (size_t)n * HC + 2 * lane) = o;
}

extern "C" void kernel_launch(void* const* d_in, const int* in_sizes, int n_in,
                              void* d_out, int out_size) {
    const float* x       = (const float*)d_in[0];
    const int*   ei      = (const int*)  d_in[1];
    const float* wgt     = (const float*)d_in[2];
    const float* W       = (const float*)d_in[3];
    const float* att_src = (const float*)d_in[4];
    const float* att_dst = (const float*)d_in[5];
    const float* bias    = (const float*)d_in[6];
    const float* esc     = (const float*)d_in[7];
    float* out = (float*)d_out;
    (void)in_sizes; (void)n_in; (void)out_size;

    k_gemm    <<<(NN + 127) / 128, 256>>>(x, W, att_src, att_dst);
    k_hist    <<<(EE + 255) / 256, 256>>>(ei, wgt);
    k_scan    <<<NB,               256>>>();
    k_scatter <<<(EE + 255) / 256, 256>>>(ei);
    k_gather  <<<(NN + 7) / 8,     256>>>(out, bias, esc);
}

// round 8
// speedup vs baseline: 1.5355x; 1.5355x over previous
#include <cuda_runtime.h>
#include <cuda_fp16.h>
#include <math.h>

#define NN 50000
#define EE 1600000
#define DD 128
#define HC 64     // H*C = 2*32
#define NB 196    // ceil(NN/256) scan blocks

// ---- scratch (device globals; no allocation allowed) ----
__device__ __half  g_hh[NN * HC];       // fp16 h = elu(x) @ W      6.4 MB
__device__ float   g_asrc[NN * 2];
__device__ float   g_adst[NN * 2];
__device__ float2  g_nwcnt[NN];         // {sum w, count} per source node
__device__ int     g_deg[NN];           // in-degree (excl self loop)
__device__ int     g_off[NN];           // block-local exclusive scan
__device__ int     g_cursor[NN];        // scatter cursors (end-of-segment after scatter)
__device__ int     g_bsum[256];
__device__ int     g_bsumx[256];
__device__ uint2   g_sorted[EE];        // {src, as01:half2}  12.8 MB

__device__ __forceinline__ float lrelu(float a) { return a > 0.0f ? a : 0.2f * a; }
__device__ __forceinline__ float elu_f(float v) { return v > 0.0f ? v : (__expf(v) - 1.0f); }

__device__ __forceinline__ void fma4(float4& acc, const float4 wv, const float xs) {
    acc.x += xs * wv.x; acc.y += xs * wv.y; acc.z += xs * wv.z; acc.w += xs * wv.w;
}
__device__ __forceinline__ float dot4(const float4 a, const float4 b) {
    return a.x*b.x + a.y*b.y + a.z*b.z + a.w*b.w;
}

// ---------------- 1) h = elu(x) @ W, register-blocked 4x8, fused attention dots ----------------
__global__ void k_gemm(const float* __restrict__ x, const float* __restrict__ W,
                       const float* __restrict__ att_src, const float* __restrict__ att_dst) {
    __shared__ float sW[DD * HC];                 // 32 KB
    __shared__ float sAs[HC], sAd[HC];
    int tid = threadIdx.x;                        // 256 threads
    const float4* Wv = (const float4*)W;
    float4* sWv = (float4*)sW;
#pragma unroll
    for (int i = 0; i < 8; i++) sWv[tid + i * 256] = Wv[tid + i * 256];
    if (tid < HC) { sAs[tid] = att_src[tid]; sAd[tid] = att_dst[tid]; }
    __syncthreads();

    int cg = tid & 7;                             // 8 cols starting at cg*8
    int rg = tid >> 3;                            // 0..31, 4 rows each
    int rb = blockIdx.x * 128 + rg * 4;

    float4 a[4][2];
#pragma unroll
    for (int i = 0; i < 4; i++) { a[i][0] = make_float4(0,0,0,0); a[i][1] = make_float4(0,0,0,0); }

    const float4* xp[4];
#pragma unroll
    for (int i = 0; i < 4; i++) {
        int r = rb + i; if (r >= NN) r = NN - 1;
        xp[i] = (const float4*)(x + (size_t)r * DD);
    }

#pragma unroll 2
    for (int k4 = 0; k4 < 32; k4++) {
        float4 xv[4];
#pragma unroll
        for (int i = 0; i < 4; i++) {
            float4 v = __ldg(&xp[i][k4]);
            v.x = elu_f(v.x); v.y = elu_f(v.y); v.z = elu_f(v.z); v.w = elu_f(v.w);
            xv[i] = v;
        }
#pragma unroll
        for (int j = 0; j < 4; j++) {
            const float4* wr = (const float4*)&sW[(k4 * 4 + j) * HC + cg * 8];
            float4 w0 = wr[0], w1 = wr[1];
#pragma unroll
            for (int i = 0; i < 4; i++) {
                float xs = (j == 0) ? xv[i].x : (j == 1) ? xv[i].y : (j == 2) ? xv[i].z : xv[i].w;
                fma4(a[i][0], w0, xs);
                fma4(a[i][1], w1, xs);
            }
        }
    }

    float4 s0 = ((const float4*)sAs)[cg * 2], s1 = ((const float4*)sAs)[cg * 2 + 1];
    float4 d0 = ((const float4*)sAd)[cg * 2], d1 = ((const float4*)sAd)[cg * 2 + 1];
    float asp[4], adp[4];
#pragma unroll
    for (int i = 0; i < 4; i++) {
        asp[i] = dot4(a[i][0], s0) + dot4(a[i][1], s1);
        adp[i] = dot4(a[i][0], d0) + dot4(a[i][1], d1);
    }
#pragma unroll
    for (int off = 1; off <= 2; off <<= 1) {
#pragma unroll
        for (int i = 0; i < 4; i++) {
            asp[i] += __shfl_xor_sync(0xffffffff, asp[i], off);
            adp[i] += __shfl_xor_sync(0xffffffff, adp[i], off);
        }
    }
    if ((cg & 3) == 0) {
        int head = cg >> 2;
#pragma unroll
        for (int i = 0; i < 4; i++) {
            int r = rb + i;
            if (r < NN) {
                g_asrc[2*r + head] = asp[i];
                g_adst[2*r + head] = adp[i];
                if (head == 0) { g_nwcnt[r] = make_float2(0.0f, 0.0f); g_deg[r] = 0; }
            }
        }
    }

#pragma unroll
    for (int i = 0; i < 4; i++) {
        int r = rb + i;
        if (r < NN) {
            __half2* hp = (__half2*)(g_hh + (size_t)r * HC + cg * 8);
            hp[0] = __floats2half2_rn(a[i][0].x, a[i][0].y);
            hp[1] = __floats2half2_rn(a[i][0].z, a[i][0].w);
            hp[2] = __floats2half2_rn(a[i][1].x, a[i][1].y);
            hp[3] = __floats2half2_rn(a[i][1].z, a[i][1].w);
        }
    }
}

// ---------------- 2) histogram: deg[dst]++, nwcnt[src] += {w,1} ----------------
__global__ void k_hist(const int* __restrict__ ei, const float* __restrict__ wgt) {
    int e = blockIdx.x * blockDim.x + threadIdx.x;
    if (e >= EE) return;
    int s = __ldg(&ei[e]);
    int d = __ldg(&ei[EE + e]);
    atomicAdd(&g_deg[d], 1);
    float w = __ldg(&wgt[e]);
    asm volatile("red.global.add.v2.f32 [%0], {%1,%2};"
                 :: "l"((float*)(g_nwcnt + s)), "f"(w), "f"(1.0f) : "memory");
}

// ---------------- 3) shuffle-based 3-step exclusive scan ----------------
__global__ void k_scan1() {
    int tid = threadIdx.x, lane = tid & 31, w = tid >> 5;
    int i = blockIdx.x * 256 + tid;
    int v = (i < NN) ? g_deg[i] : 0;
    int s = v;
#pragma unroll
    for (int off = 1; off < 32; off <<= 1) {
        int t = __shfl_up_sync(0xffffffff, s, off);
        if (lane >= off) s += t;
    }
    __shared__ int ws[8];
    if (lane == 31) ws[w] = s;
    __syncthreads();
    int woff = 0;
#pragma unroll
    for (int k = 0; k < 8; k++) woff += (k < w) ? ws[k] : 0;
    if (i < NN) g_off[i] = s - v + woff;
    if (tid == 255) g_bsum[blockIdx.x] = s + woff;
}
__global__ void k_scan2() {
    int tid = threadIdx.x, lane = tid & 31, w = tid >> 5;
    int v = (tid < NB) ? g_bsum[tid] : 0;
    int s = v;
#pragma unroll
    for (int off = 1; off < 32; off <<= 1) {
        int t = __shfl_up_sync(0xffffffff, s, off);
        if (lane >= off) s += t;
    }
    __shared__ int ws[8];
    if (lane == 31) ws[w] = s;
    __syncthreads();
    int woff = 0;
#pragma unroll
    for (int k = 0; k < 8; k++) woff += (k < w) ? ws[k] : 0;
    g_bsumx[tid] = s - v + woff;
}
__global__ void k_scan3() {
    int i = blockIdx.x * 256 + threadIdx.x;
    if (i >= NN) return;
    g_cursor[i] = g_off[i] + g_bsumx[blockIdx.x];
}

// ---------------- 4) scatter: 8B records {src, as01:half2} sorted by dst ----------------
__global__ void k_scatter(const int* __restrict__ ei) {
    int e = blockIdx.x * blockDim.x + threadIdx.x;
    if (e >= EE) return;
    int s = __ldg(&ei[e]);
    int d = __ldg(&ei[EE + e]);
    float2 as = __ldg((const float2*)(g_asrc + 2 * s));
    __half2 ah = __floats2half2_rn(as.x, as.y);
    uint2 rec;
    rec.x = (unsigned)s;
    rec.y = *(unsigned*)&ah;
    int pos = atomicAdd(&g_cursor[d], 1);
    g_sorted[pos] = rec;
}

// ---------------- 5) gather: one warp per dst, exp via lane-slot trick, pipelined ----------------
__global__ void k_gather(float* __restrict__ out, const float* __restrict__ bias,
                         const float* __restrict__ esc) {
    int warp_in_block = threadIdx.x >> 5;
    int lane = threadIdx.x & 31;
    int n = blockIdx.x * 8 + warp_in_block;
    if (n >= NN) return;

    int head = lane >> 4;                 // lanes 0-15: head0, 16-31: head1
    int cnt   = g_deg[n];
    int start = g_cursor[n] - cnt;        // cursor is end-of-segment after scatter

    float2 adv = __ldg((const float2*)(g_adst + 2 * n));
    int t  = lane & 7;
    int qq = t >> 1;                      // record slot this lane computes exp for
    int hs = t & 1;                       // head slot
    float ad_sel = hs ? adv.y : adv.x;
    float ad_me  = head ? adv.y : adv.x;

    float2 acc = make_float2(0.0f, 0.0f);
    float den = 0.0f;
    const __half2* hh = (const __half2*)g_hh;
    const uint2* rec = g_sorted + start;

    int nq = cnt >> 2, rem = cnt & 3;
    uint2 r0, r1, r2, r3;
    if (nq) { r0 = __ldg(rec); r1 = __ldg(rec + 1); r2 = __ldg(rec + 2); r3 = __ldg(rec + 3); }
    for (int q = 0; q < nq; q++) {
        __half2 v0 = __ldg(hh + (size_t)r0.x * 32 + lane);
        __half2 v1 = __ldg(hh + (size_t)r1.x * 32 + lane);
        __half2 v2 = __ldg(hh + (size_t)r2.x * 32 + lane);
        __half2 v3 = __ldg(hh + (size_t)r3.x * 32 + lane);

        // one warp-wide exp computes all 8 (record, head) slots in lanes 0-7
        unsigned ab = (qq == 0) ? r0.y : (qq == 1) ? r1.y : (qq == 2) ? r2.y : r3.y;
        float2 af = __half22float2(*(__half2*)&ab);
        float ev = __expf(lrelu((hs ? af.y : af.x) + ad_sel));
        float e0 = __shfl_sync(0xffffffff, ev, head);
        float e1 = __shfl_sync(0xffffffff, ev, 2 + head);
        float e2 = __shfl_sync(0xffffffff, ev, 4 + head);
        float e3 = __shfl_sync(0xffffffff, ev, 6 + head);

        bool more = (q + 1 < nq);
        uint2 n0, n1, n2, n3;
        if (more) {
            const uint2* p = rec + 4 * (q + 1);
            n0 = __ldg(p); n1 = __ldg(p + 1); n2 = __ldg(p + 2); n3 = __ldg(p + 3);
        }
        float2 f0 = __half22float2(v0);
        float2 f1 = __half22float2(v1);
        float2 f2 = __half22float2(v2);
        float2 f3 = __half22float2(v3);
        acc.x += e0 * f0.x + e1 * f1.x + e2 * f2.x + e3 * f3.x;
        acc.y += e0 * f0.y + e1 * f1.y + e2 * f2.y + e3 * f3.y;
        den   += (e0 + e1) + (e2 + e3);
        if (more) { r0 = n0; r1 = n1; r2 = n2; r3 = n3; }
    }
    const uint2* tp = rec + nq * 4;
    for (int k = 0; k < rem; k++) {
        uint2 r = __ldg(tp + k);
        __half2 v = __ldg(hh + (size_t)r.x * 32 + lane);
        float2 af = __half22float2(*(__half2*)&r.y);
        float e0 = __expf(lrelu((head ? af.y : af.x) + ad_me));
        float2 f = __half22float2(v);
        acc.x += e0 * f.x; acc.y += e0 * f.y;
        den += e0;
    }

    // self loop (fp32 logits)
    float a_self = lrelu(g_asrc[2*n + head] + ad_me);
    float e_self = __expf(a_self);
    float2 hsv = __half22float2(__ldg(hh + (size_t)n * 32 + lane));
    acc.x += e_self * hsv.x; acc.y += e_self * hsv.y;
    den += e_self;

    float rd = __frcp_rn(den);

    float2 nwc = g_nwcnt[n];
    float nw = nwc.x / fmaxf(nwc.y, 1.0f);
    nw = fminf(fmaxf(nw, 0.2f), 5.0f);
    float sf  = 0.1f / (1.0f + __expf(-esc[0]));
    float add = sf * (nw - 1.0f);

    float2 b2 = *(const float2*)(bias + 2 * lane);
    float2 o;
    o.x = acc.x * rd + b2.x + add;
    o.y = acc.y * rd + b2.y + add;
    *(float2*)(out + (size_t)n * HC + 2 * lane) = o;
}

extern "C" void kernel_launch(void* const* d_in, const int* in_sizes, int n_in,
                              void* d_out, int out_size) {
    const float* x       = (const float*)d_in[0];
    const int*   ei      = (const int*)  d_in[1];
    const float* wgt     = (const float*)d_in[2];
    const float* W       = (const float*)d_in[3];
    const float* att_src = (const float*)d_in[4];
    const float* att_dst = (const float*)d_in[5];
    const float* bias    = (const float*)d_in[6];
    const float* esc     = (const float*)d_in[7];
    float* out = (float*)d_out;
    (void)in_sizes; (void)n_in; (void)out_size;

    k_gemm    <<<(NN + 127) / 128, 256>>>(x, W, att_src, att_dst);
    k_hist    <<<(EE + 255) / 256, 256>>>(ei, wgt);
    k_scan1   <<<NB,               256>>>();
    k_scan2   <<<1,                256>>>();
    k_scan3   <<<NB,               256>>>();
    k_scatter <<<(EE + 255) / 256, 256>>>(ei);
    k_gather  <<<(NN + 7) / 8,     256>>>(out, bias, esc);
}

// round 9
// speedup vs baseline: 1.5402x; 1.0030x over previous
#include <cuda_runtime.h>
#include <cuda_fp16.h>
#include <math.h>

#define NN 50000
#define EE 1600000
#define DD 128
#define HC 64     // H*C = 2*32
#define NB 196    // ceil(NN/256) scan blocks

// ---- scratch (device globals; no allocation allowed) ----
__device__ __half  g_hh[NN * HC];       // fp16 h = elu(x) @ W      6.4 MB
__device__ float   g_asrc[NN * 2];
__device__ float   g_adst[NN * 2];
__device__ float2  g_nwcnt[NN];         // {sum w, count} per source node
__device__ int     g_deg[NN];           // in-degree (excl self loop)
__device__ int     g_off[NN];           // block-local exclusive scan
__device__ int     g_cursor[NN];        // scatter cursors (end-of-segment after scatter)
__device__ int     g_bsum[256];
__device__ uint2   g_sorted[EE];        // {src, as01:half2}  12.8 MB

__device__ __forceinline__ float lrelu(float a) { return a > 0.0f ? a : 0.2f * a; }
__device__ __forceinline__ float elu_f(float v) { return v > 0.0f ? v : (__expf(v) - 1.0f); }

__device__ __forceinline__ void fma4(float4& acc, const float4 wv, const float xs) {
    acc.x += xs * wv.x; acc.y += xs * wv.y; acc.z += xs * wv.z; acc.w += xs * wv.w;
}
__device__ __forceinline__ float dot4(const float4 a, const float4 b) {
    return a.x*b.x + a.y*b.y + a.z*b.z + a.w*b.w;
}

// ---------------- 1) h = elu(x) @ W, register-blocked 4x8, fused attention dots ----------------
__global__ void k_gemm(const float* __restrict__ x, const float* __restrict__ W,
                       const float* __restrict__ att_src, const float* __restrict__ att_dst) {
    __shared__ float sW[DD * HC];                 // 32 KB
    __shared__ float sAs[HC], sAd[HC];
    int tid = threadIdx.x;                        // 256 threads
    const float4* Wv = (const float4*)W;
    float4* sWv = (float4*)sW;
#pragma unroll
    for (int i = 0; i < 8; i++) sWv[tid + i * 256] = Wv[tid + i * 256];
    if (tid < HC) { sAs[tid] = att_src[tid]; sAd[tid] = att_dst[tid]; }
    __syncthreads();

    int cg = tid & 7;                             // 8 cols starting at cg*8
    int rg = tid >> 3;                            // 0..31, 4 rows each
    int rb = blockIdx.x * 128 + rg * 4;

    float4 a[4][2];
#pragma unroll
    for (int i = 0; i < 4; i++) { a[i][0] = make_float4(0,0,0,0); a[i][1] = make_float4(0,0,0,0); }

    const float4* xp[4];
#pragma unroll
    for (int i = 0; i < 4; i++) {
        int r = rb + i; if (r >= NN) r = NN - 1;
        xp[i] = (const float4*)(x + (size_t)r * DD);
    }

#pragma unroll 2
    for (int k4 = 0; k4 < 32; k4++) {
        float4 xv[4];
#pragma unroll
        for (int i = 0; i < 4; i++) {
            float4 v = __ldg(&xp[i][k4]);
            v.x = elu_f(v.x); v.y = elu_f(v.y); v.z = elu_f(v.z); v.w = elu_f(v.w);
            xv[i] = v;
        }
#pragma unroll
        for (int j = 0; j < 4; j++) {
            const float4* wr = (const float4*)&sW[(k4 * 4 + j) * HC + cg * 8];
            float4 w0 = wr[0], w1 = wr[1];
#pragma unroll
            for (int i = 0; i < 4; i++) {
                float xs = (j == 0) ? xv[i].x : (j == 1) ? xv[i].y : (j == 2) ? xv[i].z : xv[i].w;
                fma4(a[i][0], w0, xs);
                fma4(a[i][1], w1, xs);
            }
        }
    }

    float4 s0 = ((const float4*)sAs)[cg * 2], s1 = ((const float4*)sAs)[cg * 2 + 1];
    float4 d0 = ((const float4*)sAd)[cg * 2], d1 = ((const float4*)sAd)[cg * 2 + 1];
    float asp[4], adp[4];
#pragma unroll
    for (int i = 0; i < 4; i++) {
        asp[i] = dot4(a[i][0], s0) + dot4(a[i][1], s1);
        adp[i] = dot4(a[i][0], d0) + dot4(a[i][1], d1);
    }
#pragma unroll
    for (int off = 1; off <= 2; off <<= 1) {
#pragma unroll
        for (int i = 0; i < 4; i++) {
            asp[i] += __shfl_xor_sync(0xffffffff, asp[i], off);
            adp[i] += __shfl_xor_sync(0xffffffff, adp[i], off);
        }
    }
    if ((cg & 3) == 0) {
        int head = cg >> 2;
#pragma unroll
        for (int i = 0; i < 4; i++) {
            int r = rb + i;
            if (r < NN) {
                g_asrc[2*r + head] = asp[i];
                g_adst[2*r + head] = adp[i];
                if (head == 0) { g_nwcnt[r] = make_float2(0.0f, 0.0f); g_deg[r] = 0; }
            }
        }
    }

#pragma unroll
    for (int i = 0; i < 4; i++) {
        int r = rb + i;
        if (r < NN) {
            __half2* hp = (__half2*)(g_hh + (size_t)r * HC + cg * 8);
            hp[0] = __floats2half2_rn(a[i][0].x, a[i][0].y);
            hp[1] = __floats2half2_rn(a[i][0].z, a[i][0].w);
            hp[2] = __floats2half2_rn(a[i][1].x, a[i][1].y);
            hp[3] = __floats2half2_rn(a[i][1].z, a[i][1].w);
        }
    }
}

// ---------------- 2) histogram (2 edges/thread): deg[dst]++, nwcnt[src] += {w,1} ----------------
__global__ void k_hist(const int* __restrict__ ei, const float* __restrict__ wgt) {
    int e2 = blockIdx.x * blockDim.x + threadIdx.x;
    if (e2 >= EE / 2) return;
    int2   ss = __ldg((const int2*)ei + e2);
    int2   dd = __ldg((const int2*)(ei + EE) + e2);
    float2 ww = __ldg((const float2*)wgt + e2);
    atomicAdd(&g_deg[dd.x], 1);
    atomicAdd(&g_deg[dd.y], 1);
    asm volatile("red.global.add.v2.f32 [%0], {%1,%2};"
                 :: "l"((float*)(g_nwcnt + ss.x)), "f"(ww.x), "f"(1.0f) : "memory");
    asm volatile("red.global.add.v2.f32 [%0], {%1,%2};"
                 :: "l"((float*)(g_nwcnt + ss.y)), "f"(ww.y), "f"(1.0f) : "memory");
}

// ---------------- 3) two-kernel scan ----------------
__global__ void k_scan1() {
    int tid = threadIdx.x, lane = tid & 31, w = tid >> 5;
    int i = blockIdx.x * 256 + tid;
    int v = (i < NN) ? g_deg[i] : 0;
    int s = v;
#pragma unroll
    for (int off = 1; off < 32; off <<= 1) {
        int t = __shfl_up_sync(0xffffffff, s, off);
        if (lane >= off) s += t;
    }
    __shared__ int ws[8];
    if (lane == 31) ws[w] = s;
    __syncthreads();
    int woff = 0;
#pragma unroll
    for (int k = 0; k < 8; k++) woff += (k < w) ? ws[k] : 0;
    if (i < NN) g_off[i] = s - v + woff;
    if (tid == 255) g_bsum[blockIdx.x] = s + woff;
}
// block b adds sum(bsum[0..b-1]) — a reduction, not a scan
__global__ void k_scan3() {
    __shared__ int ws[8];
    int tid = threadIdx.x, lane = tid & 31, w = tid >> 5;
    int b = blockIdx.x;
    int v = (tid < b) ? g_bsum[tid] : 0;   // b <= NB-1 < 256
#pragma unroll
    for (int off = 16; off >= 1; off >>= 1) v += __shfl_xor_sync(0xffffffff, v, off);
    if (lane == 0) ws[w] = v;
    __syncthreads();
    int prev = 0;
#pragma unroll
    for (int k = 0; k < 8; k++) prev += ws[k];
    int i = b * 256 + tid;
    if (i < NN) g_cursor[i] = g_off[i] + prev;
}

// ---------------- 4) scatter: 8B records {src, as01:half2} sorted by dst ----------------
__global__ void k_scatter(const int* __restrict__ ei) {
    int e = blockIdx.x * blockDim.x + threadIdx.x;
    if (e >= EE) return;
    int s = __ldg(&ei[e]);
    int d = __ldg(&ei[EE + e]);
    float2 as = __ldg((const float2*)(g_asrc + 2 * s));
    __half2 ah = __floats2half2_rn(as.x, as.y);
    uint2 rec;
    rec.x = (unsigned)s;
    rec.y = *(unsigned*)&ah;
    int pos = atomicAdd(&g_cursor[d], 1);
    g_sorted[pos] = rec;
}

// ---------------- 5) gather: one warp per dst, 8-record batches, pipelined ----------------
__global__ void k_gather(float* __restrict__ out, const float* __restrict__ bias,
                         const float* __restrict__ esc) {
    int warp_in_block = threadIdx.x >> 5;
    int lane = threadIdx.x & 31;
    int n = blockIdx.x * 8 + warp_in_block;
    if (n >= NN) return;

    int head = lane >> 4;                 // lanes 0-15: head0, 16-31: head1
    int cnt   = g_deg[n];
    int start = g_cursor[n] - cnt;        // cursor is end-of-segment after scatter

    float2 adv = __ldg((const float2*)(g_adst + 2 * n));
    int t16 = lane & 15;
    int qq  = t16 >> 1;                   // record slot (0..7) this lane exps
    int hs  = t16 & 1;                    // head slot
    float ad_sel = hs ? adv.y : adv.x;
    float ad_me  = head ? adv.y : adv.x;

    float2 acc = make_float2(0.0f, 0.0f);
    float den = 0.0f;
    const __half2* hh = (const __half2*)g_hh;
    const uint2* rec = g_sorted + start;

    int nq = cnt >> 3, rem = cnt & 7;
    uint2 r[8];
    if (nq) {
#pragma unroll
        for (int i = 0; i < 8; i++) r[i] = __ldg(rec + i);
    }
    for (int q = 0; q < nq; q++) {
        __half2 v[8];
#pragma unroll
        for (int i = 0; i < 8; i++) v[i] = __ldg(hh + (size_t)r[i].x * 32 + lane);

        // one warp-wide exp covers all 16 (record, head) slots in lanes 0-15
        unsigned ab = r[0].y;
#pragma unroll
        for (int i = 1; i < 8; i++) ab = (qq == i) ? r[i].y : ab;
        float2 af = __half22float2(*(__half2*)&ab);
        float ev = __expf(lrelu((hs ? af.y : af.x) + ad_sel));
        float e[8];
#pragma unroll
        for (int i = 0; i < 8; i++) e[i] = __shfl_sync(0xffffffff, ev, 2 * i + head);

        bool more = (q + 1 < nq);
        uint2 nr[8];
        if (more) {
            const uint2* p = rec + 8 * (q + 1);
#pragma unroll
            for (int i = 0; i < 8; i++) nr[i] = __ldg(p + i);
        }
#pragma unroll
        for (int i = 0; i < 8; i++) {
            float2 f = __half22float2(v[i]);
            acc.x += e[i] * f.x;
            acc.y += e[i] * f.y;
            den   += e[i];
        }
        if (more) {
#pragma unroll
            for (int i = 0; i < 8; i++) r[i] = nr[i];
        }
    }
    const uint2* tp = rec + nq * 8;
    for (int k = 0; k < rem; k++) {
        uint2 rr = __ldg(tp + k);
        __half2 v = __ldg(hh + (size_t)rr.x * 32 + lane);
        float2 af = __half22float2(*(__half2*)&rr.y);
        float e0 = __expf(lrelu((head ? af.y : af.x) + ad_me));
        float2 f = __half22float2(v);
        acc.x += e0 * f.x; acc.y += e0 * f.y;
        den += e0;
    }

    // self loop (fp32 logits)
    float a_self = lrelu(g_asrc[2*n + head] + ad_me);
    float e_self = __expf(a_self);
    float2 hsv = __half22float2(__ldg(hh + (size_t)n * 32 + lane));
    acc.x += e_self * hsv.x; acc.y += e_self * hsv.y;
    den += e_self;

    float rd = __frcp_rn(den);

    float2 nwc = g_nwcnt[n];
    float nw = nwc.x / fmaxf(nwc.y, 1.0f);
    nw = fminf(fmaxf(nw, 0.2f), 5.0f);
    float sf  = 0.1f / (1.0f + __expf(-esc[0]));
    float add = sf * (nw - 1.0f);

    float2 b2 = *(const float2*)(bias + 2 * lane);
    float2 o;
    o.x = acc.x * rd + b2.x + add;
    o.y = acc.y * rd + b2.y + add;
    *(float2*)(out + (size_t)n * HC + 2 * lane) = o;
}

extern "C" void kernel_launch(void* const* d_in, const int* in_sizes, int n_in,
                              void* d_out, int out_size) {
    const float* x       = (const float*)d_in[0];
    const int*   ei      = (const int*)  d_in[1];
    const float* wgt     = (const float*)d_in[2];
    const float* W       = (const float*)d_in[3];
    const float* att_src = (const float*)d_in[4];
    const float* att_dst = (const float*)d_in[5];
    const float* bias    = (const float*)d_in[6];
    const float* esc     = (const float*)d_in[7];
    float* out = (float*)d_out;
    (void)in_sizes; (void)n_in; (void)out_size;

    k_gemm    <<<(NN + 127) / 128,     256>>>(x, W, att_src, att_dst);
    k_hist    <<<(EE / 2 + 255) / 256, 256>>>(ei, wgt);
    k_scan1   <<<NB,                   256>>>();
    k_scan3   <<<NB,                   256>>>();
    k_scatter <<<(EE + 255) / 256,     256>>>(ei);
    k_gather  <<<(NN + 7) / 8,         256>>>(out, bias, esc);
}